// round 4
// baseline (speedup 1.0000x reference)
#include <cuda_runtime.h>
#include <math.h>

#define Nn 50000
#define Ee 800000
#define ETOT 850000
#define Hh 96
#define Gg 64
#define NCLS 4
#define BNEPS 1e-5f

typedef unsigned long long ull;

// packed fp32x2 helpers (sm_103a FFMA2 — only reachable via PTX)
#define FMA_F32X2(acc, a, b) \
    asm("fma.rn.f32x2 %0, %1, %2, %0;" : "+l"(acc) : "l"(a), "l"(b))
#define PACK_DUP_F32(d, f) \
    asm("mov.b64 %0, {%1, %1};" : "=l"(d) : "f"(f))
#define UNPACK_F32X2(lo, hi, u) \
    asm("mov.b64 {%0, %1}, %2;" : "=f"(lo), "=f"(hi) : "l"(u))

// ---------------- device scratch ----------------
__device__ float g_h[Nn * Hh];
__device__ float g_id[Nn * Hh];
__device__ float g_hp[Nn * Hh];
__device__ float g_tmp[Nn * Hh];
__device__ float g_ss[Nn], g_sd[Nn];
__device__ float g_ew[ETOT];
__device__ int   g_deg[Nn];
__device__ int   g_rs[Nn + 1];
__device__ int   g_cur[Nn];
__device__ int   g_csr[ETOT];
__device__ float g_bnsum[3 * Hh], g_bnsq[3 * Hh];
__device__ float g_pooled[Gg * Hh];
__device__ float g_cnt[Gg];

__device__ __forceinline__ float lrelu01(float v) { return v >= 0.f ? v : 0.01f * v; }

// ---------------- zero / init ----------------
__global__ void zero_k() {
    int i = blockIdx.x * blockDim.x + threadIdx.x;
    int stride = gridDim.x * blockDim.x;
    for (int j = i; j < Nn; j += stride) g_deg[j] = 0;
    if (i < Gg * Hh) g_pooled[i] = 0.f;
    if (i < Gg) g_cnt[i] = 0.f;
    if (i < 3 * Hh) { g_bnsum[i] = 0.f; g_bnsq[i] = 0.f; }
}

// ---------------- CSR build ----------------
__global__ void count_k(const int* __restrict__ ei) {
    int i = blockIdx.x * blockDim.x + threadIdx.x;
    if (i >= ETOT) return;
    int d = (i < Ee) ? ei[Ee + i] : (i - Ee);
    atomicAdd(&g_deg[d], 1);
}

__global__ void scan_k() {
    __shared__ int part[1024];
    int t = threadIdx.x;
    const int CH = (Nn + 1023) / 1024;
    int base = t * CH;
    int s = 0;
    for (int i = 0; i < CH; i++) {
        int idx = base + i;
        if (idx < Nn) s += g_deg[idx];
    }
    part[t] = s;
    __syncthreads();
    for (int off = 1; off < 1024; off <<= 1) {
        int v = (t >= off) ? part[t - off] : 0;
        __syncthreads();
        part[t] += v;
        __syncthreads();
    }
    int run = (t == 0) ? 0 : part[t - 1];
    for (int i = 0; i < CH; i++) {
        int idx = base + i;
        if (idx < Nn) {
            g_rs[idx] = run;
            g_cur[idx] = run;
            run += g_deg[idx];
        }
    }
    if (t == blockDim.x - 1) g_rs[Nn] = part[blockDim.x - 1];
}

__global__ void scatter_k(const int* __restrict__ ei) {
    int i = blockIdx.x * blockDim.x + threadIdx.x;
    if (i >= ETOT) return;
    int sN, dN;
    if (i < Ee) { sN = ei[i]; dN = ei[Ee + i]; }
    else        { sN = i - Ee; dN = i - Ee; }
    int pos = atomicAdd(&g_cur[dN], 1);
    g_csr[pos] = sN;
}

// ---------------- GEMM: C[M,96] = act(A'[M,K] @ W[K,96] + bias) ----------------
// tile 128x96, 384 threads, micro-tile 8x4 done as 4 row-pairs via FFMA2.
// MODE==1: A' = lrelu(bn(A)) + A2 fused on A-load (K must be 96).
// SCORES==1: also emits per-row ss = row.a_s, sd = row.a_d.
template <int ACT, int MODE, int DUP, int SCORES>
__global__ __launch_bounds__(384, 2) void gemm128(
    const float* __restrict__ A, const float* __restrict__ A2,
    const float* __restrict__ gma, const float* __restrict__ bta,
    const float* __restrict__ sumP, const float* __restrict__ sqP,
    const float* __restrict__ W, const float* __restrict__ bias,
    const float* __restrict__ as_, const float* __restrict__ ad_,
    float* __restrict__ ssO, float* __restrict__ sdO,
    float* __restrict__ C, float* __restrict__ C2, int M, int K)
{
    __shared__ float Ash[32][132];   // [k][m]
    __shared__ float Wsh[32][96];
    __shared__ float s_sc[96], s_sh[96];
    __shared__ float sS[128], sD[128];
    int tid = threadIdx.x;
    if (MODE == 1) {
        if (tid < 96) {
            float mu = sumP[tid] * (1.f / Nn);
            float var = sqP[tid] * (1.f / Nn) - mu * mu;
            float is = rsqrtf(var + BNEPS);
            float gv = gma[tid];
            s_sc[tid] = gv * is;
            s_sh[tid] = bta[tid] - mu * gv * is;
        }
        __syncthreads();
    }
    if (SCORES) {
        if (tid < 128) { sS[tid] = 0.f; sD[tid] = 0.f; }
    }
    int cg = tid % 24;               // cols cg*4..+3
    int rg = tid / 24;               // rows rg*8..+7
    int rowBase = blockIdx.x * 128;
    ull acc2[4][4];
    #pragma unroll
    for (int p = 0; p < 4; p++)
        #pragma unroll
        for (int j = 0; j < 4; j++) acc2[p][j] = 0ull;

    for (int kc = 0; kc < K; kc += 32) {
        for (int idx = tid; idx < 1024; idx += 384) {
            int m = idx >> 3, kq = idx & 7;
            int r = rowBase + m;
            float4 v = make_float4(0.f, 0.f, 0.f, 0.f);
            if (r < M) {
                v = *(const float4*)&A[r * K + kc + kq * 4];
                if (MODE == 1) {
                    float4 u = *(const float4*)&A2[r * K + kc + kq * 4];
                    int c = kc + kq * 4;
                    v.x = lrelu01(fmaf(v.x, s_sc[c + 0], s_sh[c + 0])) + u.x;
                    v.y = lrelu01(fmaf(v.y, s_sc[c + 1], s_sh[c + 1])) + u.y;
                    v.z = lrelu01(fmaf(v.z, s_sc[c + 2], s_sh[c + 2])) + u.z;
                    v.w = lrelu01(fmaf(v.w, s_sc[c + 3], s_sh[c + 3])) + u.w;
                }
            }
            int k0 = kq * 4;
            Ash[k0 + 0][m] = v.x;
            Ash[k0 + 1][m] = v.y;
            Ash[k0 + 2][m] = v.z;
            Ash[k0 + 3][m] = v.w;
        }
        #pragma unroll
        for (int j = 0; j < 8; j++) {
            int idx = tid + j * 384;
            int k = idx / 96, c = idx % 96;
            Wsh[k][c] = W[(kc + k) * 96 + c];
        }
        __syncthreads();
        #pragma unroll
        for (int k = 0; k < 32; k++) {
            // A row-pairs: 2x LDS.128 over [rg*8 .. rg*8+7]
            ulonglong2 a01 = *(const ulonglong2*)&Ash[k][rg * 8];
            ulonglong2 a23 = *(const ulonglong2*)&Ash[k][rg * 8 + 4];
            float4 w = *(const float4*)&Wsh[k][cg * 4];
            ull wd0, wd1, wd2, wd3;
            PACK_DUP_F32(wd0, w.x);
            PACK_DUP_F32(wd1, w.y);
            PACK_DUP_F32(wd2, w.z);
            PACK_DUP_F32(wd3, w.w);
            ull ap[4] = {a01.x, a01.y, a23.x, a23.y};
            #pragma unroll
            for (int p = 0; p < 4; p++) {
                FMA_F32X2(acc2[p][0], ap[p], wd0);
                FMA_F32X2(acc2[p][1], ap[p], wd1);
                FMA_F32X2(acc2[p][2], ap[p], wd2);
                FMA_F32X2(acc2[p][3], ap[p], wd3);
            }
        }
        __syncthreads();
    }
    int c0 = cg * 4;
    float bv[4];
    #pragma unroll
    for (int j = 0; j < 4; j++) bv[j] = bias ? bias[c0 + j] : 0.f;
    float asv[4], adv[4];
    if (SCORES) {
        #pragma unroll
        for (int j = 0; j < 4; j++) { asv[j] = as_[c0 + j]; adv[j] = ad_[c0 + j]; }
    }
    int r0 = rowBase + rg * 8;
    #pragma unroll
    for (int p = 0; p < 4; p++) {
        float ve[4], vo[4];
        #pragma unroll
        for (int j = 0; j < 4; j++) UNPACK_F32X2(ve[j], vo[j], acc2[p][j]);
        #pragma unroll
        for (int e = 0; e < 2; e++) {
            float* v = e ? vo : ve;
            int r = r0 + 2 * p + e;
            if (r < M) {
                if (SCORES) {
                    float s1 = v[0] * asv[0] + v[1] * asv[1] + v[2] * asv[2] + v[3] * asv[3];
                    float s2 = v[0] * adv[0] + v[1] * adv[1] + v[2] * adv[2] + v[3] * adv[3];
                    int lr = rg * 8 + 2 * p + e;
                    atomicAdd(&sS[lr], s1);
                    atomicAdd(&sD[lr], s2);
                }
                float v0 = v[0] + bv[0], v1 = v[1] + bv[1], v2 = v[2] + bv[2], v3 = v[3] + bv[3];
                if (ACT) { v0 = lrelu01(v0); v1 = lrelu01(v1); v2 = lrelu01(v2); v3 = lrelu01(v3); }
                float4 o = make_float4(v0, v1, v2, v3);
                *(float4*)&C[r * 96 + c0] = o;
                if (DUP) *(float4*)&C2[r * 96 + c0] = o;
            }
        }
    }
    if (SCORES) {
        __syncthreads();
        if (tid < 128) {
            int r = rowBase + tid;
            if (r < M) { ssO[r] = sS[tid]; sdO[r] = sD[tid]; }
        }
    }
}

// ---------------- GAT aggregation (warp/dst) + fused BN stats ----------------
// max-free softmax: scores are BN-bounded, exp(e) cannot overflow.
__global__ void agg_k(const float* __restrict__ hp,
                      const float* __restrict__ ss, const float* __restrict__ sd,
                      const float* __restrict__ bias, float* __restrict__ out,
                      float* __restrict__ sumP, float* __restrict__ sqP)
{
    __shared__ float bs[96], bq[96];
    int tid = threadIdx.x;
    if (tid < 96) { bs[tid] = 0.f; bq[tid] = 0.f; }
    __syncthreads();
    int d = (blockIdx.x * blockDim.x + tid) >> 5;
    int lane = tid & 31;
    if (d < Nn) {
        int s0 = g_rs[d], s1e = g_rs[d + 1];
        float sdd = sd[d];
        // pass 1: denominator + cache numerators
        float denom = 0.f;
        for (int j = s0 + lane; j < s1e; j += 32) {
            int s = g_csr[j];
            float e = ss[s] + sdd;
            e = (e >= 0.f) ? e : 0.2f * e;
            float wv = __expf(e);
            g_ew[j] = wv;
            denom += wv;
        }
        #pragma unroll
        for (int o = 16; o; o >>= 1) denom += __shfl_xor_sync(0xffffffffu, denom, o);
        float inv = 1.f / denom;
        // pass 2: weighted feature aggregation
        float a0 = 0.f, a1 = 0.f, a2 = 0.f;
        for (int j = s0; j < s1e; j++) {
            int s = g_csr[j];
            float wgt = g_ew[j] * inv;
            const float* row = hp + s * 96;
            a0 = fmaf(wgt, row[lane], a0);
            a1 = fmaf(wgt, row[lane + 32], a1);
            a2 = fmaf(wgt, row[lane + 64], a2);
        }
        float v0 = a0 + bias[lane];
        float v1 = a1 + bias[lane + 32];
        float v2 = a2 + bias[lane + 64];
        out[d * 96 + lane]      = v0;
        out[d * 96 + lane + 32] = v1;
        out[d * 96 + lane + 64] = v2;
        atomicAdd(&bs[lane], v0);       atomicAdd(&bq[lane], v0 * v0);
        atomicAdd(&bs[lane + 32], v1);  atomicAdd(&bq[lane + 32], v1 * v1);
        atomicAdd(&bs[lane + 64], v2);  atomicAdd(&bq[lane + 64], v2 * v2);
    }
    __syncthreads();
    if (tid < 96) {
        atomicAdd(&sumP[tid], bs[tid]);
        atomicAdd(&sqP[tid], bq[tid]);
    }
}

// ---------------- fused BN-apply + Poincare expmap0 + segment pooling ----------------
__global__ void expool_k(const float* __restrict__ t, const float* __restrict__ idn,
                         const float* __restrict__ gma, const float* __restrict__ bta,
                         const float* __restrict__ sumP, const float* __restrict__ sqP,
                         const int* __restrict__ batch)
{
    __shared__ float sp[Gg * Hh];
    __shared__ float scn[Gg];
    __shared__ float s_sc[96], s_sh[96];
    if (threadIdx.x < 96) {
        int c = threadIdx.x;
        float mu = sumP[c] * (1.f / Nn);
        float var = sqP[c] * (1.f / Nn) - mu * mu;
        float is = rsqrtf(var + BNEPS);
        float gv = gma[c];
        s_sc[c] = gv * is;
        s_sh[c] = bta[c] - mu * gv * is;
    }
    for (int i = threadIdx.x; i < Gg * Hh; i += blockDim.x) sp[i] = 0.f;
    if (threadIdx.x < Gg) scn[threadIdx.x] = 0.f;
    __syncthreads();
    int lane = threadIdx.x & 31;
    int warp = (blockIdx.x * blockDim.x + threadIdx.x) >> 5;
    int nwarps = (gridDim.x * blockDim.x) >> 5;
    for (int n = warp; n < Nn; n += nwarps) {
        float v0 = lrelu01(fmaf(t[n * 96 + lane],      s_sc[lane],      s_sh[lane]))      + idn[n * 96 + lane];
        float v1 = lrelu01(fmaf(t[n * 96 + lane + 32], s_sc[lane + 32], s_sh[lane + 32])) + idn[n * 96 + lane + 32];
        float v2 = lrelu01(fmaf(t[n * 96 + lane + 64], s_sc[lane + 64], s_sh[lane + 64])) + idn[n * 96 + lane + 64];
        float q = v0 * v0 + v1 * v1 + v2 * v2;
        #pragma unroll
        for (int o = 16; o; o >>= 1) q += __shfl_xor_sync(0xffffffffu, q, o);
        float nrm = fmaxf(sqrtf(q), 1e-15f);
        float s = tanhf(nrm) / nrm;
        int g = batch[n];
        atomicAdd(&sp[g * 96 + lane], v0 * s);
        atomicAdd(&sp[g * 96 + lane + 32], v1 * s);
        atomicAdd(&sp[g * 96 + lane + 64], v2 * s);
        if (lane == 0) atomicAdd(&scn[g], 1.f);
    }
    __syncthreads();
    for (int i = threadIdx.x; i < Gg * Hh; i += blockDim.x) atomicAdd(&g_pooled[i], sp[i]);
    if (threadIdx.x < Gg) atomicAdd(&g_cnt[threadIdx.x], scn[threadIdx.x]);
}

// ---------------- head ----------------
__global__ void head_k(const float* __restrict__ fc3W, const float* __restrict__ fc3b,
                       const float* __restrict__ fc4W, const float* __restrict__ fc4b,
                       float* __restrict__ out)
{
    __shared__ float p[Gg * Hh];
    __shared__ float o1[Gg * 48];
    for (int i = threadIdx.x; i < Gg * Hh; i += blockDim.x) {
        int g = i / 96;
        p[i] = g_pooled[i] / fmaxf(g_cnt[g], 1.f);
    }
    __syncthreads();
    for (int i = threadIdx.x; i < Gg * 48; i += blockDim.x) {
        int g = i / 48, c = i % 48;
        float a = fc3b[c];
        for (int k = 0; k < 96; k++) a = fmaf(p[g * 96 + k], fc3W[k * 48 + c], a);
        o1[i] = lrelu01(a);
    }
    __syncthreads();
    for (int i = threadIdx.x; i < Gg * NCLS; i += blockDim.x) {
        int g = i / NCLS, c = i % NCLS;
        float a = fc4b[c];
        for (int k = 0; k < 48; k++) a = fmaf(o1[g * 48 + k], fc4W[k * NCLS + c], a);
        out[i] = a;
    }
}

// ---------------- launch ----------------
extern "C" void kernel_launch(void* const* d_in, const int* in_sizes, int n_in,
                              void* d_out, int out_size)
{
    const float* x     = (const float*)d_in[0];
    const int*   ei    = (const int*)d_in[1];
    const int*   batch = (const int*)d_in[2];
    const float* embW  = (const float*)d_in[3];
    const float* embB  = (const float*)d_in[4];
    const float* cW[3]  = {(const float*)d_in[5],  (const float*)d_in[9],  (const float*)d_in[13]};
    const float* cAS[3] = {(const float*)d_in[6],  (const float*)d_in[10], (const float*)d_in[14]};
    const float* cAD[3] = {(const float*)d_in[7],  (const float*)d_in[11], (const float*)d_in[15]};
    const float* cB[3]  = {(const float*)d_in[8],  (const float*)d_in[12], (const float*)d_in[16]};
    const float* fcW[2] = {(const float*)d_in[17], (const float*)d_in[19]};
    const float* fcB[2] = {(const float*)d_in[18], (const float*)d_in[20]};
    const float* bnG[3] = {(const float*)d_in[21], (const float*)d_in[23], (const float*)d_in[25]};
    const float* bnB[3] = {(const float*)d_in[22], (const float*)d_in[24], (const float*)d_in[26]};
    const float* fc3W = (const float*)d_in[27];
    const float* fc3b = (const float*)d_in[28];
    const float* fc4W = (const float*)d_in[29];
    const float* fc4b = (const float*)d_in[30];
    float* out = (float*)d_out;

    float *ph, *pid, *php, *ptmp, *pss, *psd, *pbs, *pbq;
    cudaGetSymbolAddress((void**)&ph,   g_h);
    cudaGetSymbolAddress((void**)&pid,  g_id);
    cudaGetSymbolAddress((void**)&php,  g_hp);
    cudaGetSymbolAddress((void**)&ptmp, g_tmp);
    cudaGetSymbolAddress((void**)&pss,  g_ss);
    cudaGetSymbolAddress((void**)&psd,  g_sd);
    cudaGetSymbolAddress((void**)&pbs,  g_bnsum);
    cudaGetSymbolAddress((void**)&pbq,  g_bnsq);

    const int EB = (ETOT + 255) / 256;
    const int GB = (Nn + 127) / 128;
    const int WB = (Nn * 32 + 255) / 256;

    // Fork: CSR build concurrent with embed GEMM. Streams/events intentionally
    // leaked (destroying them mid-capture would abort graph capture).
    cudaStream_t s1;
    cudaStreamCreateWithFlags(&s1, cudaStreamNonBlocking);
    cudaEvent_t evFork, evJoin;
    cudaEventCreateWithFlags(&evFork, cudaEventDisableTiming);
    cudaEventCreateWithFlags(&evJoin, cudaEventDisableTiming);

    cudaEventRecord(evFork, 0);
    cudaStreamWaitEvent(s1, evFork, 0);
    zero_k<<<256, 256, 0, s1>>>();
    count_k<<<EB, 256, 0, s1>>>(ei);
    scan_k<<<1, 1024, 0, s1>>>();
    scatter_k<<<EB, 256, 0, s1>>>(ei);
    cudaEventRecord(evJoin, s1);

    // embed: h = lrelu(x @ embW + embB); identity = h
    gemm128<1, 0, 1, 0><<<GB, 384>>>(x, nullptr, nullptr, nullptr, nullptr, nullptr,
                                     embW, embB, nullptr, nullptr, nullptr, nullptr,
                                     ph, pid, Nn, 256);

    for (int l = 0; l < 3; l++) {
        // hp = h @ cW  (+ fused attention scores)
        gemm128<0, 0, 0, 1><<<GB, 384>>>(ph, nullptr, nullptr, nullptr, nullptr, nullptr,
                                         cW[l], nullptr, cAS[l], cAD[l], pss, psd,
                                         php, nullptr, Nn, 96);
        if (l == 0) cudaStreamWaitEvent(0, evJoin, 0);   // CSR + zeroed BN slots ready
        agg_k<<<WB, 256>>>(php, pss, psd, cB[l], ptmp, pbs + l * Hh, pbq + l * Hh);
        if (l < 2) {
            // h = lrelu( (lrelu(bn(tmp)) + id) @ fcW + fcB ) — BN fused into A-load
            gemm128<1, 1, 0, 0><<<GB, 384>>>(ptmp, pid, bnG[l], bnB[l], pbs + l * Hh, pbq + l * Hh,
                                             fcW[l], fcB[l], nullptr, nullptr, nullptr, nullptr,
                                             ph, nullptr, Nn, 96);
        }
    }

    expool_k<<<160, 256>>>(ptmp, pid, bnG[2], bnB[2], pbs + 2 * Hh, pbq + 2 * Hh, batch);
    head_k<<<1, 256>>>(fc3W, fc3b, fc4W, fc4b, out);
}